// round 3
// baseline (speedup 1.0000x reference)
#include <cuda_runtime.h>
#include <math.h>

// Problem dims
#define HD    1024          // hidden
#define EMBD  128           // embedding
#define FQ    512           // flat sequences (B*E)
#define LQ    128           // max char len
#define BQ    128           // programs
#define PQ    1024          // program vocab
#define PLENQ 16
#define N4    4096          // 4*HD (gate dim)
#define KCH   (EMBD + HD)   // 1152, char-LSTM fused K

// GEMM tiling
#define BM 64
#define BN 64
#define BK 16
#define NT 256

// ---------------- scratch (static device globals; no allocation) ----------------
__device__ float g_hA[FQ * HD];
__device__ float g_hB[FQ * HD];
__device__ float g_c [FQ * HD];
__device__ float g_Wt_in [KCH * N4];   // [K=1152][4096] gate-interleaved
__device__ float g_Wt_out[KCH * N4];
__device__ float g_Wt_ihp[HD * N4];    // [1024][4096] gate-interleaved
__device__ float g_Wt_hhp[HD * N4];
__device__ float g_bg_in[N4];
__device__ float g_bg_out[N4];
__device__ float g_bg_p[N4];
__device__ float g_XP[FQ * N4];        // prev_h @ W_ih_p^T + b_p (constant over PLEN)
__device__ float g_Wt_mp[HD * HD];     // [K][N] plain transpose
__device__ float g_Wt_sm[HD * PQ];
__device__ float g_pooled[BQ * HD];

__device__ __forceinline__ float sigf(float x) { return 1.f / (1.f + expf(-x)); }

// ---------------- init / weight reshaping ----------------
__global__ void k_zero_state() {
    int i = blockIdx.x * blockDim.x + threadIdx.x;
    if (i < FQ * HD) { g_hA[i] = 0.f; g_c[i] = 0.f; }
}

// Combined char-LSTM weights: Wt[k][j*4+g] = (k<EMBD)? Wih[(g*HD+j)*EMBD+k] : Whh[(g*HD+j)*HD+(k-EMBD)]
__global__ void k_reorder_lstm(const float* __restrict__ Wih, const float* __restrict__ Whh, int which) {
    float* Wt = which ? g_Wt_out : g_Wt_in;
    int idx = blockIdx.x * blockDim.x + threadIdx.x;
    if (idx >= KCH * N4) return;
    int k = idx >> 12;          // / 4096
    int n = idx & 4095;
    int j = n >> 2, g = n & 3;
    int row = g * HD + j;
    Wt[idx] = (k < EMBD) ? Wih[row * EMBD + k] : Whh[row * HD + (k - EMBD)];
}

// Program-LSTM weights (K=1024), gate-interleaved
__global__ void k_reorder_gate1024(const float* __restrict__ W, int which) {
    float* Wt = which ? g_Wt_hhp : g_Wt_ihp;
    int idx = blockIdx.x * blockDim.x + threadIdx.x;
    if (idx >= HD * N4) return;
    int k = idx >> 12;
    int n = idx & 4095;
    int j = n >> 2, g = n & 3;
    Wt[idx] = W[(g * HD + j) * HD + k];
}

__global__ void k_transpose1024(const float* __restrict__ W, int which) {
    float* Wt = which ? g_Wt_sm : g_Wt_mp;
    int idx = blockIdx.x * blockDim.x + threadIdx.x;
    if (idx >= HD * HD) return;
    int k = idx >> 10;
    int n = idx & 1023;
    Wt[idx] = W[n * HD + k];
}

__global__ void k_reorder_bias(const float* __restrict__ b, int which) {
    float* bg = (which == 0) ? g_bg_in : (which == 1) ? g_bg_out : g_bg_p;
    int n = blockIdx.x * blockDim.x + threadIdx.x;
    if (n >= N4) return;
    int j = n >> 2, g = n & 3;
    bg[n] = b[g * HD + j];
}

// ---------------- fused char-LSTM step: gates GEMM (K=1152, emb gather) + cell ----------------
__global__ __launch_bounds__(NT)
void k_lstm_char(const int* __restrict__ tokens, const int* __restrict__ lengths,
                 const float* __restrict__ emb, int t, int sel, int wsel) {
    const float* __restrict__ hin  = sel ? g_hB : g_hA;
    float* __restrict__       hout = sel ? g_hA : g_hB;
    const float* __restrict__ Wt = wsel ? g_Wt_out : g_Wt_in;
    const float* __restrict__ bg = wsel ? g_bg_out : g_bg_in;

    __shared__ float As[BK][BM + 4];
    __shared__ float Bs[BK][BN];
    __shared__ int   stok[BM];
    __shared__ int   slen[BM];

    int tid = threadIdx.x;
    int m0 = blockIdx.y * BM;
    int n0 = blockIdx.x * BN;

    if (tid < BM) {
        stok[tid] = tokens[(m0 + tid) * LQ + t];
        slen[tid] = lengths[m0 + tid];
    }
    __syncthreads();

    float acc[4][4] = {};
    int ma = tid >> 2;            // 0..63 (A row)
    int k4 = (tid & 3) * 4;       // A k offset
    int kb = tid >> 4;            // B k row
    int n4 = (tid & 15) * 4;      // B n offset
    int ty = tid >> 4, tx = tid & 15;

    for (int k0 = 0; k0 < KCH; k0 += BK) {
        float4 av;
        if (k0 < EMBD) av = *(const float4*)(emb + stok[ma] * EMBD + k0 + k4);
        else           av = *(const float4*)(hin + (m0 + ma) * HD + (k0 - EMBD) + k4);
        float4 bv = *(const float4*)(Wt + (k0 + kb) * N4 + n0 + n4);
        As[k4 + 0][ma] = av.x; As[k4 + 1][ma] = av.y;
        As[k4 + 2][ma] = av.z; As[k4 + 3][ma] = av.w;
        *(float4*)&Bs[kb][n4] = bv;
        __syncthreads();
        #pragma unroll
        for (int k = 0; k < BK; k++) {
            float4 a = *(const float4*)&As[k][ty * 4];
            float4 b = *(const float4*)&Bs[k][tx * 4];
            acc[0][0] += a.x * b.x; acc[0][1] += a.x * b.y; acc[0][2] += a.x * b.z; acc[0][3] += a.x * b.w;
            acc[1][0] += a.y * b.x; acc[1][1] += a.y * b.y; acc[1][2] += a.y * b.z; acc[1][3] += a.y * b.w;
            acc[2][0] += a.z * b.x; acc[2][1] += a.z * b.y; acc[2][2] += a.z * b.z; acc[2][3] += a.z * b.w;
            acc[3][0] += a.w * b.x; acc[3][1] += a.w * b.y; acc[3][2] += a.w * b.z; acc[3][3] += a.w * b.w;
        }
        __syncthreads();
    }

    int j = (n0 >> 2) + tx;   // hidden unit index
    float4 bb = *(const float4*)(bg + n0 + tx * 4);
    #pragma unroll
    for (int r = 0; r < 4; r++) {
        int ml = ty * 4 + r;
        int m = m0 + ml;
        float gi = acc[r][0] + bb.x;
        float gf = acc[r][1] + bb.y;
        float gg = acc[r][2] + bb.z;
        float go = acc[r][3] + bb.w;
        int idx = m * HD + j;
        float cp = g_c[idx];
        float cn = sigf(gf) * cp + sigf(gi) * tanhf(gg);
        float hn = sigf(go) * tanhf(cn);
        if (t < slen[ml]) { g_c[idx] = cn; hout[idx] = hn; }
        else              { hout[idx] = hin[idx]; }
    }
}

// ---------------- XP = prev_h @ W_ih_p^T + b_p  (gate-interleaved layout) ----------------
__global__ __launch_bounds__(NT)
void k_xp(int sel) {
    const float* __restrict__ hin = sel ? g_hB : g_hA;
    __shared__ float As[BK][BM + 4];
    __shared__ float Bs[BK][BN];
    int tid = threadIdx.x;
    int m0 = blockIdx.y * BM, n0 = blockIdx.x * BN;
    float acc[4][4] = {};
    int ma = tid >> 2, k4 = (tid & 3) * 4;
    int kb = tid >> 4, n4 = (tid & 15) * 4;
    int ty = tid >> 4, tx = tid & 15;
    for (int k0 = 0; k0 < HD; k0 += BK) {
        float4 av = *(const float4*)(hin + (m0 + ma) * HD + k0 + k4);
        float4 bv = *(const float4*)(g_Wt_ihp + (k0 + kb) * N4 + n0 + n4);
        As[k4 + 0][ma] = av.x; As[k4 + 1][ma] = av.y;
        As[k4 + 2][ma] = av.z; As[k4 + 3][ma] = av.w;
        *(float4*)&Bs[kb][n4] = bv;
        __syncthreads();
        #pragma unroll
        for (int k = 0; k < BK; k++) {
            float4 a = *(const float4*)&As[k][ty * 4];
            float4 b = *(const float4*)&Bs[k][tx * 4];
            acc[0][0] += a.x * b.x; acc[0][1] += a.x * b.y; acc[0][2] += a.x * b.z; acc[0][3] += a.x * b.w;
            acc[1][0] += a.y * b.x; acc[1][1] += a.y * b.y; acc[1][2] += a.y * b.z; acc[1][3] += a.y * b.w;
            acc[2][0] += a.z * b.x; acc[2][1] += a.z * b.y; acc[2][2] += a.z * b.z; acc[2][3] += a.z * b.w;
            acc[3][0] += a.w * b.x; acc[3][1] += a.w * b.y; acc[3][2] += a.w * b.z; acc[3][3] += a.w * b.w;
        }
        __syncthreads();
    }
    float4 bb = *(const float4*)(g_bg_p + n0 + tx * 4);
    #pragma unroll
    for (int r = 0; r < 4; r++) {
        int m = m0 + ty * 4 + r;
        float4 v;
        v.x = acc[r][0] + bb.x; v.y = acc[r][1] + bb.y;
        v.z = acc[r][2] + bb.z; v.w = acc[r][3] + bb.w;
        *(float4*)(g_XP + m * N4 + n0 + tx * 4) = v;
    }
}

// ---------------- program-LSTM step: gates = XP + h @ W_hh_p^T, cell (no mask) ----------------
__global__ __launch_bounds__(NT)
void k_prog(int sel) {
    const float* __restrict__ hin  = sel ? g_hB : g_hA;
    float* __restrict__       hout = sel ? g_hA : g_hB;
    __shared__ float As[BK][BM + 4];
    __shared__ float Bs[BK][BN];
    int tid = threadIdx.x;
    int m0 = blockIdx.y * BM, n0 = blockIdx.x * BN;
    float acc[4][4] = {};
    int ma = tid >> 2, k4 = (tid & 3) * 4;
    int kb = tid >> 4, n4 = (tid & 15) * 4;
    int ty = tid >> 4, tx = tid & 15;
    for (int k0 = 0; k0 < HD; k0 += BK) {
        float4 av = *(const float4*)(hin + (m0 + ma) * HD + k0 + k4);
        float4 bv = *(const float4*)(g_Wt_hhp + (k0 + kb) * N4 + n0 + n4);
        As[k4 + 0][ma] = av.x; As[k4 + 1][ma] = av.y;
        As[k4 + 2][ma] = av.z; As[k4 + 3][ma] = av.w;
        *(float4*)&Bs[kb][n4] = bv;
        __syncthreads();
        #pragma unroll
        for (int k = 0; k < BK; k++) {
            float4 a = *(const float4*)&As[k][ty * 4];
            float4 b = *(const float4*)&Bs[k][tx * 4];
            acc[0][0] += a.x * b.x; acc[0][1] += a.x * b.y; acc[0][2] += a.x * b.z; acc[0][3] += a.x * b.w;
            acc[1][0] += a.y * b.x; acc[1][1] += a.y * b.y; acc[1][2] += a.y * b.z; acc[1][3] += a.y * b.w;
            acc[2][0] += a.z * b.x; acc[2][1] += a.z * b.y; acc[2][2] += a.z * b.z; acc[2][3] += a.z * b.w;
            acc[3][0] += a.w * b.x; acc[3][1] += a.w * b.y; acc[3][2] += a.w * b.z; acc[3][3] += a.w * b.w;
        }
        __syncthreads();
    }
    int j = (n0 >> 2) + tx;
    #pragma unroll
    for (int r = 0; r < 4; r++) {
        int m = m0 + ty * 4 + r;
        float4 xp = *(const float4*)(g_XP + m * N4 + n0 + tx * 4);
        float gi = acc[r][0] + xp.x;
        float gf = acc[r][1] + xp.y;
        float gg = acc[r][2] + xp.z;
        float go = acc[r][3] + xp.w;
        int idx = m * HD + j;
        float cp = g_c[idx];
        float cn = sigf(gf) * cp + sigf(gi) * tanhf(gg);
        float hn = sigf(go) * tanhf(cn);
        g_c[idx] = cn;
        hout[idx] = hn;
    }
}

// ---------------- max-pool linear: pooled[b] = max_e tanh(h @ W_mp^T + b_mp) ----------------
__global__ __launch_bounds__(NT)
void k_mp(const float* __restrict__ bmp, int sel) {
    const float* __restrict__ hcur = sel ? g_hB : g_hA;
    __shared__ float As[BK][BM + 4];
    __shared__ float Bs[BK][BN];
    int tid = threadIdx.x;
    int m0 = blockIdx.y * BM, n0 = blockIdx.x * BN;
    float acc[4][4] = {};
    int ma = tid >> 2, k4 = (tid & 3) * 4;
    int kb = tid >> 4, n4 = (tid & 15) * 4;
    int ty = tid >> 4, tx = tid & 15;
    for (int k0 = 0; k0 < HD; k0 += BK) {
        float4 av = *(const float4*)(hcur + (m0 + ma) * HD + k0 + k4);
        float4 bv = *(const float4*)(g_Wt_mp + (k0 + kb) * HD + n0 + n4);
        As[k4 + 0][ma] = av.x; As[k4 + 1][ma] = av.y;
        As[k4 + 2][ma] = av.z; As[k4 + 3][ma] = av.w;
        *(float4*)&Bs[kb][n4] = bv;
        __syncthreads();
        #pragma unroll
        for (int k = 0; k < BK; k++) {
            float4 a = *(const float4*)&As[k][ty * 4];
            float4 b = *(const float4*)&Bs[k][tx * 4];
            acc[0][0] += a.x * b.x; acc[0][1] += a.x * b.y; acc[0][2] += a.x * b.z; acc[0][3] += a.x * b.w;
            acc[1][0] += a.y * b.x; acc[1][1] += a.y * b.y; acc[1][2] += a.y * b.z; acc[1][3] += a.y * b.w;
            acc[2][0] += a.z * b.x; acc[2][1] += a.z * b.y; acc[2][2] += a.z * b.z; acc[2][3] += a.z * b.w;
            acc[3][0] += a.w * b.x; acc[3][1] += a.w * b.y; acc[3][2] += a.w * b.z; acc[3][3] += a.w * b.w;
        }
        __syncthreads();
    }
    // rows m0+ty*4 .. +3 are examples of one program b = m0/4 + ty
    float4 bb = *(const float4*)(bmp + n0 + tx * 4);
    float4 mx;
    mx.x = mx.y = mx.z = mx.w = -2.f;  // tanh in [-1,1]
    #pragma unroll
    for (int r = 0; r < 4; r++) {
        float ux = tanhf(acc[r][0] + bb.x);
        float uy = tanhf(acc[r][1] + bb.y);
        float uz = tanhf(acc[r][2] + bb.z);
        float uw = tanhf(acc[r][3] + bb.w);
        mx.x = fmaxf(mx.x, ux); mx.y = fmaxf(mx.y, uy);
        mx.z = fmaxf(mx.z, uz); mx.w = fmaxf(mx.w, uw);
    }
    int b = (m0 >> 2) + ty;
    *(float4*)(g_pooled + b * HD + n0 + tx * 4) = mx;
}

// ---------------- logits: out[s] = pooled @ W_sm^T + b_sm ----------------
__global__ __launch_bounds__(NT)
void k_logits(const float* __restrict__ bsm, float* __restrict__ out, int s) {
    __shared__ float As[BK][BM + 4];
    __shared__ float Bs[BK][BN];
    int tid = threadIdx.x;
    int m0 = blockIdx.y * BM, n0 = blockIdx.x * BN;
    float acc[4][4] = {};
    int ma = tid >> 2, k4 = (tid & 3) * 4;
    int kb = tid >> 4, n4 = (tid & 15) * 4;
    int ty = tid >> 4, tx = tid & 15;
    for (int k0 = 0; k0 < HD; k0 += BK) {
        float4 av = *(const float4*)(g_pooled + (m0 + ma) * HD + k0 + k4);
        float4 bv = *(const float4*)(g_Wt_sm + (k0 + kb) * PQ + n0 + n4);
        As[k4 + 0][ma] = av.x; As[k4 + 1][ma] = av.y;
        As[k4 + 2][ma] = av.z; As[k4 + 3][ma] = av.w;
        *(float4*)&Bs[kb][n4] = bv;
        __syncthreads();
        #pragma unroll
        for (int k = 0; k < BK; k++) {
            float4 a = *(const float4*)&As[k][ty * 4];
            float4 b = *(const float4*)&Bs[k][tx * 4];
            acc[0][0] += a.x * b.x; acc[0][1] += a.x * b.y; acc[0][2] += a.x * b.z; acc[0][3] += a.x * b.w;
            acc[1][0] += a.y * b.x; acc[1][1] += a.y * b.y; acc[1][2] += a.y * b.z; acc[1][3] += a.y * b.w;
            acc[2][0] += a.z * b.x; acc[2][1] += a.z * b.y; acc[2][2] += a.z * b.z; acc[2][3] += a.z * b.w;
            acc[3][0] += a.w * b.x; acc[3][1] += a.w * b.y; acc[3][2] += a.w * b.z; acc[3][3] += a.w * b.w;
        }
        __syncthreads();
    }
    float4 bb = *(const float4*)(bsm + n0 + tx * 4);
    #pragma unroll
    for (int r = 0; r < 4; r++) {
        int m = m0 + ty * 4 + r;
        float4 v;
        v.x = acc[r][0] + bb.x; v.y = acc[r][1] + bb.y;
        v.z = acc[r][2] + bb.z; v.w = acc[r][3] + bb.w;
        *(float4*)(out + (size_t)s * BQ * PQ + m * PQ + n0 + tx * 4) = v;
    }
}

// ---------------- host orchestration ----------------
extern "C" void kernel_launch(void* const* d_in, const int* in_sizes, int n_in,
                              void* d_out, int out_size) {
    const int*   tokens_in   = (const int*)d_in[0];
    const int*   lengths_in  = (const int*)d_in[1];
    const int*   tokens_out  = (const int*)d_in[2];
    const int*   lengths_out = (const int*)d_in[3];
    const float* emb         = (const float*)d_in[4];
    const float* W_ih_in     = (const float*)d_in[5];
    const float* W_hh_in     = (const float*)d_in[6];
    const float* b_in        = (const float*)d_in[7];
    const float* W_ih_out    = (const float*)d_in[8];
    const float* W_hh_out    = (const float*)d_in[9];
    const float* b_out       = (const float*)d_in[10];
    const float* W_ih_p      = (const float*)d_in[11];
    const float* W_hh_p      = (const float*)d_in[12];
    const float* b_p         = (const float*)d_in[13];
    const float* W_mp        = (const float*)d_in[14];
    const float* b_mp        = (const float*)d_in[15];
    const float* W_sm        = (const float*)d_in[16];
    const float* b_sm        = (const float*)d_in[17];
    float* out = (float*)d_out;

    // init + weight reorder (every call; deterministic)
    k_zero_state<<<(FQ * HD + 255) / 256, 256>>>();
    k_reorder_lstm<<<(KCH * N4 + 255) / 256, 256>>>(W_ih_in,  W_hh_in,  0);
    k_reorder_lstm<<<(KCH * N4 + 255) / 256, 256>>>(W_ih_out, W_hh_out, 1);
    k_reorder_gate1024<<<(HD * N4 + 255) / 256, 256>>>(W_ih_p, 0);
    k_reorder_gate1024<<<(HD * N4 + 255) / 256, 256>>>(W_hh_p, 1);
    k_transpose1024<<<(HD * HD + 255) / 256, 256>>>(W_mp, 0);
    k_transpose1024<<<(HD * PQ + 255) / 256, 256>>>(W_sm, 1);
    k_reorder_bias<<<(N4 + 255) / 256, 256>>>(b_in, 0);
    k_reorder_bias<<<(N4 + 255) / 256, 256>>>(b_out, 1);
    k_reorder_bias<<<(N4 + 255) / 256, 256>>>(b_p, 2);

    dim3 gridG(N4 / BN, FQ / BM);   // 64 x 8 for gate GEMMs

    int cur = 0;  // 0: current h in g_hA
    for (int t = 0; t < LQ; t++) {
        k_lstm_char<<<gridG, NT>>>(tokens_in, lengths_in, emb, t, cur, 0);
        cur ^= 1;
    }
    for (int t = 0; t < LQ; t++) {
        k_lstm_char<<<gridG, NT>>>(tokens_out, lengths_out, emb, t, cur, 1);
        cur ^= 1;
    }

    // program decoder
    k_xp<<<gridG, NT>>>(cur);
    dim3 gridMP(HD / BN, FQ / BM);   // 16 x 8
    dim3 gridLG(PQ / BN, BQ / BM);   // 16 x 2
    for (int s = 0; s < PLENQ; s++) {
        k_prog<<<gridG, NT>>>(cur);
        cur ^= 1;
        k_mp<<<gridMP, NT>>>(b_mp, cur);
        k_logits<<<gridLG, NT>>>(b_sm, out, s);
    }
}

// round 6
// speedup vs baseline: 4.1673x; 4.1673x over previous
#include <cuda_runtime.h>
#include <cuda_fp16.h>
#include <math.h>
#include <stdint.h>

// Problem dims
#define HD    1024
#define EMBD  128
#define FQ    512
#define LQ    128
#define BQ    128
#define PQ    1024
#define PLENQ 16
#define N4    4096

// MMA GEMM tiling
#define TM 128          // CTA M tile
#define TN 128          // CTA N tile
#define BKH 64          // K per stage (halfs) -> 128B rows, SW128 swizzle
#define NSTG 3
#define KTILES (HD / BKH)   // 16
#define STAGE_BYTES (TM*BKH*2 + TN*BKH*2)   // 16KB + 16KB
#define SMEM_DYN (NSTG * STAGE_BYTES)       // 96KB

// SIMT GEMM tiling (xp / mp / logits)
#define BM 64
#define BN 64
#define BK 16
#define NT 256

// ---------------- scratch ----------------
__device__ __half g_h16A[FQ * HD];
__device__ __half g_h16B[FQ * HD];
__device__ float  g_c  [FQ * HD];
__device__ __half g_Wr_in [N4 * HD];   // [n permuted][k], fp16
__device__ __half g_Wr_out[N4 * HD];
__device__ __half g_Wr_p  [N4 * HD];
__device__ float  g_XE_in [128 * N4];  // E@W_ih^T + b, permuted cols, fp32
__device__ float  g_XE_out[128 * N4];
__device__ float  g_Wt_ihp[HD * N4];   // [k][n permuted] fp32 for XP SIMT GEMM
__device__ float  g_bg_p[N4];
__device__ float  g_XP[FQ * N4];
__device__ float  g_Wt_mp[HD * HD];
__device__ float  g_Wt_sm[HD * PQ];
__device__ float  g_pooled[BQ * HD];

__device__ __forceinline__ float sigf(float x) { return 1.f / (1.f + expf(-x)); }

// Column permutation: n -> (gate, j) matched to HMMA C-fragment ownership.
// q=n&31: tn=q>>3 (n8 tile), s=q&1, gate=(tn&1)*2+s, j=(n>>5)*8+((q>>1)&3)*2+((q>>4)&1)
__device__ __forceinline__ void colmap(int n, int& gate, int& j) {
    int q = n & 31;
    gate = ((q >> 3) & 1) * 2 + (q & 1);
    j = ((n >> 5) << 3) + (((q >> 1) & 3) << 1) + ((q >> 4) & 1);
}

// ---------------- PTX helpers ----------------
__device__ __forceinline__ uint32_t smem_u32(const void* p) {
    uint32_t a;
    asm("{ .reg .u64 t; cvta.to.shared.u64 t, %1; cvt.u32.u64 %0, t; }" : "=r"(a) : "l"(p));
    return a;
}
#define SWZ(b) ((b) ^ (((b) >> 3) & 0x70))

__device__ __forceinline__ void cp16(uint32_t dst, const void* src) {
    asm volatile("cp.async.cg.shared.global [%0], [%1], 16;" :: "r"(dst), "l"(src));
}
#define CP_COMMIT() asm volatile("cp.async.commit_group;" ::: "memory")
#define CP_WAIT1()  asm volatile("cp.async.wait_group 1;" ::: "memory")
#define CP_WAIT0()  asm volatile("cp.async.wait_group 0;" ::: "memory")

__device__ __forceinline__ void ldsm4(uint32_t (&r)[4], uint32_t addr) {
    asm volatile("ldmatrix.sync.aligned.m8n8.x4.shared.b16 {%0,%1,%2,%3}, [%4];"
                 : "=r"(r[0]), "=r"(r[1]), "=r"(r[2]), "=r"(r[3]) : "r"(addr));
}
__device__ __forceinline__ void mma16816(float (&c)[4], const uint32_t (&a)[4],
                                         uint32_t b0, uint32_t b1) {
    asm volatile(
        "mma.sync.aligned.m16n8k16.row.col.f32.f16.f16.f32 "
        "{%0,%1,%2,%3}, {%4,%5,%6,%7}, {%8,%9}, {%0,%1,%2,%3};"
        : "+f"(c[0]), "+f"(c[1]), "+f"(c[2]), "+f"(c[3])
        : "r"(a[0]), "r"(a[1]), "r"(a[2]), "r"(a[3]), "r"(b0), "r"(b1));
}

// ---------------- one-time prep ----------------
__global__ void k_zero_state() {
    int i = blockIdx.x * blockDim.x + threadIdx.x;
    if (i < FQ * HD) { g_h16A[i] = __float2half(0.f); g_c[i] = 0.f; }
}

// Wr16[n][k] = fp16(W[(gate*HD+j)*HD + k]) with permuted n
__global__ void k_conv_w(const float* __restrict__ W, int which) {
    __half* o = (which == 0) ? g_Wr_in : (which == 1) ? g_Wr_out : g_Wr_p;
    int idx = blockIdx.x * blockDim.x + threadIdx.x;
    if (idx >= N4 * HD) return;
    int n = idx >> 10, k = idx & 1023;
    int gate, j; colmap(n, gate, j);
    o[idx] = __float2half(W[(size_t)(gate * HD + j) * HD + k]);
}

// XE[v][n] = E[v] . Wih[gate*HD+j] + b[gate*HD+j]
__global__ void k_xe(const float* __restrict__ E, const float* __restrict__ Wih,
                     const float* __restrict__ b, int which) {
    float* XE = which ? g_XE_out : g_XE_in;
    int idx = blockIdx.x * blockDim.x + threadIdx.x;
    if (idx >= 128 * N4) return;
    int v = idx >> 12, n = idx & 4095;
    int gate, j; colmap(n, gate, j);
    int row = gate * HD + j;
    const float4* e = (const float4*)(E + v * EMBD);
    const float4* w = (const float4*)(Wih + (size_t)row * EMBD);
    float s = b[row];
    #pragma unroll 8
    for (int k = 0; k < EMBD / 4; k++) {
        float4 a = e[k], c = w[k];
        s += a.x * c.x + a.y * c.y + a.z * c.z + a.w * c.w;
    }
    XE[idx] = s;
}

__global__ void k_reorder_ihp(const float* __restrict__ W, const float* __restrict__ b) {
    int idx = blockIdx.x * blockDim.x + threadIdx.x;
    if (idx >= HD * N4) return;
    int k = idx >> 12, n = idx & 4095;
    int gate, j; colmap(n, gate, j);
    g_Wt_ihp[idx] = W[(size_t)(gate * HD + j) * HD + k];
    if (k == 0) g_bg_p[n] = b[gate * HD + j];
}

__global__ void k_transpose1024(const float* __restrict__ W, int which) {
    float* Wt = which ? g_Wt_sm : g_Wt_mp;
    int idx = blockIdx.x * blockDim.x + threadIdx.x;
    if (idx >= HD * HD) return;
    int k = idx >> 10, n = idx & 1023;
    Wt[idx] = W[n * HD + k];
}

// ---------------- HMMA LSTM step ----------------
// gates[512,4096] = h16 @ Wr16^T (fp32 acc) + XE[token]/XP; fused cell epilogue.
// mode 0: char-in, 1: char-out, 2: program (XP addend, no mask)
__global__ void __launch_bounds__(256, 1)
k_lstm(const int* __restrict__ tokens, const int* __restrict__ lengths,
       int t, int sel, int mode) {
    extern __shared__ char smem[];
    const __half* __restrict__ hin  = sel ? g_h16B : g_h16A;
    __half* __restrict__       hout = sel ? g_h16A : g_h16B;
    const __half* __restrict__ Wr = (mode == 0) ? g_Wr_in : (mode == 1) ? g_Wr_out : g_Wr_p;

    uint32_t sbase = smem_u32(smem);
    int tid = threadIdx.x;
    int lane = tid & 31, wid = tid >> 5;
    int wm = wid >> 2, wn = wid & 3;           // 2 x 4 warp grid
    int m0 = blockIdx.y * TM;
    int n0 = blockIdx.x * TN;

    uint32_t sA[NSTG], sB[NSTG];
    #pragma unroll
    for (int i = 0; i < NSTG; i++) {
        sA[i] = sbase + i * STAGE_BYTES;
        sB[i] = sA[i] + TM * BKH * 2;
    }

    #define LOAD_TILE(ti, st) do {                                               \
        int k0 = (ti) * BKH;                                                     \
        _Pragma("unroll")                                                        \
        for (int o = 0; o < 4; o++) {                                            \
            int chunk = tid * 4 + o;                                             \
            int row = chunk >> 3, c16 = chunk & 7;                               \
            cp16(sA[st] + SWZ(row * 128 + c16 * 16),                             \
                 hin + (size_t)(m0 + row) * HD + k0 + c16 * 8);                  \
            cp16(sB[st] + SWZ(row * 128 + c16 * 16),                             \
                 Wr + (size_t)(n0 + row) * HD + k0 + c16 * 8);                   \
        }                                                                        \
        CP_COMMIT();                                                             \
    } while (0)

    float C[4][4][4] = {};   // [mt][nt][reg]

    LOAD_TILE(0, 0);
    LOAD_TILE(1, 1);

    for (int u = 0; u < KTILES; u++) {
        int p = u % NSTG;
        if (u < KTILES - 1) CP_WAIT1(); else CP_WAIT0();
        __syncthreads();
        if (u + 2 < KTILES) LOAD_TILE(u + 2, (u + 2) % NSTG);

        uint32_t aB = sA[p], bB = sB[p];
        #pragma unroll
        for (int kk = 0; kk < 4; kk++) {
            uint32_t ra[4][4], rb[2][4];
            #pragma unroll
            for (int mt = 0; mt < 4; mt++) {
                uint32_t addr = aB + SWZ((wm * 64 + mt * 16 + (lane & 15)) * 128
                                         + (kk * 16 + (lane >> 4) * 8) * 2);
                ldsm4(ra[mt], addr);
            }
            #pragma unroll
            for (int np = 0; np < 2; np++) {
                uint32_t addr = bB + SWZ((wn * 32 + np * 16 + ((lane >> 4) & 1) * 8 + (lane & 7)) * 128
                                         + (kk * 16 + ((lane >> 3) & 1) * 8) * 2);
                ldsm4(rb[np], addr);
            }
            #pragma unroll
            for (int mt = 0; mt < 4; mt++) {
                #pragma unroll
                for (int np = 0; np < 2; np++) {
                    mma16816(C[mt][2 * np + 0], ra[mt], rb[np][0], rb[np][1]);
                    mma16816(C[mt][2 * np + 1], ra[mt], rb[np][2], rb[np][3]);
                }
            }
        }
    }

    // ---- fused LSTM cell epilogue ----
    int r0 = lane >> 2;
    int cpair = (lane & 3) * 2;
    int nwarp0 = n0 + wn * 32;
    int jbase = ((n0 >> 5) + wn) * 8 + (lane & 3) * 2;

    #pragma unroll
    for (int mt = 0; mt < 4; mt++) {
        #pragma unroll
        for (int rowsel = 0; rowsel < 2; rowsel++) {
            int m = m0 + wm * 64 + mt * 16 + r0 + rowsel * 8;
            const float* base;
            bool act = true;
            if (mode < 2) {
                int tok = tokens[m * LQ + t];
                base = (mode ? g_XE_out : g_XE_in) + (size_t)tok * N4;
                act = (t < lengths[m]);
            } else {
                base = g_XP + (size_t)m * N4;
            }
            int rg = rowsel * 2;
            size_t hidx = (size_t)m * HD + jbase;
            if (act) {
                float hv[2];
                float2 cold = *(float2*)(g_c + hidx);
                float cvals[2] = { cold.x, cold.y };
                #pragma unroll
                for (int u = 0; u < 2; u++) {
                    int n_if = nwarp0 + u * 16 + cpair;
                    float2 aif = *(const float2*)(base + n_if);
                    float2 ago = *(const float2*)(base + n_if + 8);
                    float gi = C[mt][2 * u + 0][rg + 0] + aif.x;
                    float gf = C[mt][2 * u + 0][rg + 1] + aif.y;
                    float gg = C[mt][2 * u + 1][rg + 0] + ago.x;
                    float go = C[mt][2 * u + 1][rg + 1] + ago.y;
                    float cn = sigf(gf) * cvals[u] + sigf(gi) * tanhf(gg);
                    hv[u] = sigf(go) * tanhf(cn);
                    cvals[u] = cn;
                }
                *(float2*)(g_c + hidx) = make_float2(cvals[0], cvals[1]);
                *(__half2*)(hout + hidx) = __floats2half2_rn(hv[0], hv[1]);
            } else {
                *(__half2*)(hout + hidx) = *(const __half2*)(hin + hidx);
            }
        }
    }
    #undef LOAD_TILE
}

// ---------------- SIMT GEMMs (xp / mp / logits) ----------------
__global__ __launch_bounds__(NT)
void k_xp(int sel) {
    const __half* __restrict__ hin = sel ? g_h16B : g_h16A;
    __shared__ float As[BK][BM + 4];
    __shared__ float Bs[BK][BN];
    int tid = threadIdx.x;
    int m0 = blockIdx.y * BM, n0 = blockIdx.x * BN;
    float acc[4][4] = {};
    int ma = tid >> 2, k4 = (tid & 3) * 4;
    int kb = tid >> 4, n4 = (tid & 15) * 4;
    int ty = tid >> 4, tx = tid & 15;
    for (int k0 = 0; k0 < HD; k0 += BK) {
        __half2 p0 = *(const __half2*)(hin + (m0 + ma) * HD + k0 + k4);
        __half2 p1 = *(const __half2*)(hin + (m0 + ma) * HD + k0 + k4 + 2);
        float2 f0 = __half22float2(p0), f1 = __half22float2(p1);
        float4 bv = *(const float4*)(g_Wt_ihp + (size_t)(k0 + kb) * N4 + n0 + n4);
        As[k4 + 0][ma] = f0.x; As[k4 + 1][ma] = f0.y;
        As[k4 + 2][ma] = f1.x; As[k4 + 3][ma] = f1.y;
        *(float4*)&Bs[kb][n4] = bv;
        __syncthreads();
        #pragma unroll
        for (int k = 0; k < BK; k++) {
            float4 a = *(const float4*)&As[k][ty * 4];
            float4 b = *(const float4*)&Bs[k][tx * 4];
            acc[0][0] += a.x * b.x; acc[0][1] += a.x * b.y; acc[0][2] += a.x * b.z; acc[0][3] += a.x * b.w;
            acc[1][0] += a.y * b.x; acc[1][1] += a.y * b.y; acc[1][2] += a.y * b.z; acc[1][3] += a.y * b.w;
            acc[2][0] += a.z * b.x; acc[2][1] += a.z * b.y; acc[2][2] += a.z * b.z; acc[2][3] += a.z * b.w;
            acc[3][0] += a.w * b.x; acc[3][1] += a.w * b.y; acc[3][2] += a.w * b.z; acc[3][3] += a.w * b.w;
        }
        __syncthreads();
    }
    float4 bb = *(const float4*)(g_bg_p + n0 + tx * 4);
    #pragma unroll
    for (int r = 0; r < 4; r++) {
        int m = m0 + ty * 4 + r;
        float4 v;
        v.x = acc[r][0] + bb.x; v.y = acc[r][1] + bb.y;
        v.z = acc[r][2] + bb.z; v.w = acc[r][3] + bb.w;
        *(float4*)(g_XP + (size_t)m * N4 + n0 + tx * 4) = v;
    }
}

__global__ __launch_bounds__(NT)
void k_mp(const float* __restrict__ bmp, int sel) {
    const __half* __restrict__ hcur = sel ? g_h16B : g_h16A;
    __shared__ float As[BK][BM + 4];
    __shared__ float Bs[BK][BN];
    int tid = threadIdx.x;
    int m0 = blockIdx.y * BM, n0 = blockIdx.x * BN;
    float acc[4][4] = {};
    int ma = tid >> 2, k4 = (tid & 3) * 4;
    int kb = tid >> 4, n4 = (tid & 15) * 4;
    int ty = tid >> 4, tx = tid & 15;
    for (int k0 = 0; k0 < HD; k0 += BK) {
        __half2 p0 = *(const __half2*)(hcur + (m0 + ma) * HD + k0 + k4);
        __half2 p1 = *(const __half2*)(hcur + (m0 + ma) * HD + k0 + k4 + 2);
        float2 f0 = __half22float2(p0), f1 = __half22float2(p1);
        float4 bv = *(const float4*)(g_Wt_mp + (k0 + kb) * HD + n0 + n4);
        As[k4 + 0][ma] = f0.x; As[k4 + 1][ma] = f0.y;
        As[k4 + 2][ma] = f1.x; As[k4 + 3][ma] = f1.y;
        *(float4*)&Bs[kb][n4] = bv;
        __syncthreads();
        #pragma unroll
        for (int k = 0; k < BK; k++) {
            float4 a = *(const float4*)&As[k][ty * 4];
            float4 b = *(const float4*)&Bs[k][tx * 4];
            acc[0][0] += a.x * b.x; acc[0][1] += a.x * b.y; acc[0][2] += a.x * b.z; acc[0][3] += a.x * b.w;
            acc[1][0] += a.y * b.x; acc[1][1] += a.y * b.y; acc[1][2] += a.y * b.z; acc[1][3] += a.y * b.w;
            acc[2][0] += a.z * b.x; acc[2][1] += a.z * b.y; acc[2][2] += a.z * b.z; acc[2][3] += a.z * b.w;
            acc[3][0] += a.w * b.x; acc[3][1] += a.w * b.y; acc[3][2] += a.w * b.z; acc[3][3] += a.w * b.w;
        }
        __syncthreads();
    }
    float4 bb = *(const float4*)(bmp + n0 + tx * 4);
    float4 mx; mx.x = mx.y = mx.z = mx.w = -2.f;
    #pragma unroll
    for (int r = 0; r < 4; r++) {
        mx.x = fmaxf(mx.x, tanhf(acc[r][0] + bb.x));
        mx.y = fmaxf(mx.y, tanhf(acc[r][1] + bb.y));
        mx.z = fmaxf(mx.z, tanhf(acc[r][2] + bb.z));
        mx.w = fmaxf(mx.w, tanhf(acc[r][3] + bb.w));
    }
    int b = (m0 >> 2) + ty;
    *(float4*)(g_pooled + b * HD + n0 + tx * 4) = mx;
}

__global__ __launch_bounds__(NT)
void k_logits(const float* __restrict__ bsm, float* __restrict__ out, int s) {
    __shared__ float As[BK][BM + 4];
    __shared__ float Bs[BK][BN];
    int tid = threadIdx.x;
    int m0 = blockIdx.y * BM, n0 = blockIdx.x * BN;
    float acc[4][4] = {};
    int ma = tid >> 2, k4 = (tid & 3) * 4;
    int kb = tid >> 4, n4 = (tid & 15) * 4;
    int ty = tid >> 4, tx = tid & 15;
    for (int k0 = 0; k0 < HD; k0 += BK) {
        float4 av = *(const float4*)(g_pooled + (m0 + ma) * HD + k0 + k4);
        float4 bv = *(const float4*)(g_Wt_sm + (k0 + kb) * PQ + n0 + n4);
        As[k4 + 0][ma] = av.x; As[k4 + 1][ma] = av.y;
        As[k4 + 2][ma] = av.z; As[k4 + 3][ma] = av.w;
        *(float4*)&Bs[kb][n4] = bv;
        __syncthreads();
        #pragma unroll
        for (int k = 0; k < BK; k++) {
            float4 a = *(const float4*)&As[k][ty * 4];
            float4 b = *(const float4*)&Bs[k][tx * 4];
            acc[0][0] += a.x * b.x; acc[0][1] += a.x * b.y; acc[0][2] += a.x * b.z; acc[0][3] += a.x * b.w;
            acc[1][0] += a.y * b.x; acc[1][1] += a.y * b.y; acc[1][2] += a.y * b.z; acc[1][3] += a.y * b.w;
            acc[2][0] += a.z * b.x; acc[2][1] += a.z * b.y; acc[2][2] += a.z * b.z; acc[2][3] += a.z * b.w;
            acc[3][0] += a.w * b.x; acc[3][1] += a.w * b.y; acc[3][2] += a.w * b.z; acc[3][3] += a.w * b.w;
        }
        __syncthreads();
    }
    float4 bb = *(const float4*)(bsm + n0 + tx * 4);
    #pragma unroll
    for (int r = 0; r < 4; r++) {
        int m = m0 + ty * 4 + r;
        float4 v;
        v.x = acc[r][0] + bb.x; v.y = acc[r][1] + bb.y;
        v.z = acc[r][2] + bb.z; v.w = acc[r][3] + bb.w;
        *(float4*)(out + (size_t)s * BQ * PQ + m * PQ + n0 + tx * 4) = v;
    }
}

// ---------------- host orchestration ----------------
extern "C" void kernel_launch(void* const* d_in, const int* in_sizes, int n_in,
                              void* d_out, int out_size) {
    const int*   tokens_in   = (const int*)d_in[0];
    const int*   lengths_in  = (const int*)d_in[1];
    const int*   tokens_out  = (const int*)d_in[2];
    const int*   lengths_out = (const int*)d_in[3];
    const float* emb         = (const float*)d_in[4];
    const float* W_ih_in     = (const float*)d_in[5];
    const float* W_hh_in     = (const float*)d_in[6];
    const float* b_in        = (const float*)d_in[7];
    const float* W_ih_out    = (const float*)d_in[8];
    const float* W_hh_out    = (const float*)d_in[9];
    const float* b_out       = (const float*)d_in[10];
    const float* W_ih_p      = (const float*)d_in[11];
    const float* W_hh_p      = (const float*)d_in[12];
    const float* b_p         = (const float*)d_in[13];
    const float* W_mp        = (const float*)d_in[14];
    const float* b_mp        = (const float*)d_in[15];
    const float* W_sm        = (const float*)d_in[16];
    const float* b_sm        = (const float*)d_in[17];
    float* out = (float*)d_out;

    static int smem_set = 0;
    if (!smem_set) {
        cudaFuncSetAttribute(k_lstm, cudaFuncAttributeMaxDynamicSharedMemorySize, SMEM_DYN);
        smem_set = 1;
    }

    k_zero_state<<<(FQ * HD + 255) / 256, 256>>>();
    k_conv_w<<<(N4 * HD + 255) / 256, 256>>>(W_hh_in,  0);
    k_conv_w<<<(N4 * HD + 255) / 256, 256>>>(W_hh_out, 1);
    k_conv_w<<<(N4 * HD + 255) / 256, 256>>>(W_hh_p,   2);
    k_xe<<<(128 * N4 + 255) / 256, 256>>>(emb, W_ih_in,  b_in,  0);
    k_xe<<<(128 * N4 + 255) / 256, 256>>>(emb, W_ih_out, b_out, 1);
    k_reorder_ihp<<<(HD * N4 + 255) / 256, 256>>>(W_ih_p, b_p);
    k_transpose1024<<<(HD * HD + 255) / 256, 256>>>(W_mp, 0);
    k_transpose1024<<<(HD * PQ + 255) / 256, 256>>>(W_sm, 1);

    dim3 gridTC(N4 / TN, FQ / TM);   // 32 x 4 = 128 CTAs

    int cur = 0;
    for (int t = 0; t < LQ; t++) {
        k_lstm<<<gridTC, 256, SMEM_DYN>>>(tokens_in, lengths_in, t, cur, 0);
        cur ^= 1;
    }
    for (int t = 0; t < LQ; t++) {
        k_lstm<<<gridTC, 256, SMEM_DYN>>>(tokens_out, lengths_out, t, cur, 1);
        cur ^= 1;
    }

    dim3 gridG(N4 / BN, FQ / BM);
    k_xp<<<gridG, NT>>>(cur);

    dim3 gridMP(HD / BN, FQ / BM);
    dim3 gridLG(PQ / BN, BQ / BM);
    for (int s = 0; s < PLENQ; s++) {
        k_lstm<<<gridTC, 256, SMEM_DYN>>>(tokens_in, lengths_in, 0, cur, 2);
        cur ^= 1;
        k_mp<<<gridMP, NT>>>(b_mp, cur);
        k_logits<<<gridLG, NT>>>(b_sm, out, s);
    }
}

// round 7
// speedup vs baseline: 6.0033x; 1.4406x over previous
#include <cuda_runtime.h>
#include <cuda_fp16.h>
#include <math.h>
#include <stdint.h>

// Problem dims
#define HD    1024
#define EMBD  128
#define FQ    512
#define LQ    128
#define BQ    128
#define PQ    1024
#define PLENQ 16
#define N4    4096

// Persistent GEMM tiling
#define PTM 256              // M per CTA
#define PTN 64               // N per CTA (W slice resident in SMEM)
#define PBK 64               // halfs per k-tile (128B rows, SW128)
#define PKT 16               // k-tiles (HD/PBK)
#define W_BYTES (PTN * HD * 2)          // 131072
#define A_STAGE (PTM * PBK * 2)         // 32768
#define SMEM_P  (W_BYTES + 3 * A_STAGE) // 229376
#define GRIDX (N4 / PTN)     // 64
#define GRIDY (FQ / PTM)     // 2
#define NCTAS (GRIDX * GRIDY) // 128

// SIMT GEMM tiling (mp / logits)
#define BM 64
#define BN 64
#define BK 16
#define NT 256

// ---------------- scratch ----------------
__device__ __half g_h16A[FQ * HD];
__device__ __half g_h16B[FQ * HD];
__device__ float  g_c  [FQ * HD];
__device__ __half g_Wr_in [N4 * HD];   // [n permuted][k] fp16
__device__ __half g_Wr_out[N4 * HD];
__device__ __half g_Wr_p  [N4 * HD];   // W_hh_p
__device__ __half g_Wr_ihp[N4 * HD];   // W_ih_p
__device__ float  g_XE_in [128 * N4];
__device__ float  g_XE_out[128 * N4];
__device__ float  g_bg_p[N4];
__device__ float  g_XP[FQ * N4];
__device__ __half g_hsteps[PLENQ * FQ * HD];  // prog-step hidden states
__device__ float  g_Wt_mp[HD * HD];
__device__ float  g_Wt_sm[HD * PQ];
__device__ float  g_pooled[PLENQ * BQ * HD];
__device__ unsigned g_bar;

__device__ __forceinline__ float sigf(float x) { return 1.f / (1.f + expf(-x)); }

// Column permutation: n -> (gate, j) matched to HMMA C-fragment ownership.
__device__ __forceinline__ void colmap(int n, int& gate, int& j) {
    int q = n & 31;
    gate = ((q >> 3) & 1) * 2 + (q & 1);
    j = ((n >> 5) << 3) + (((q >> 1) & 3) << 1) + ((q >> 4) & 1);
}

// ---------------- PTX helpers ----------------
__device__ __forceinline__ uint32_t smem_u32(const void* p) {
    uint32_t a;
    asm("{ .reg .u64 t; cvta.to.shared.u64 t, %1; cvt.u32.u64 %0, t; }" : "=r"(a) : "l"(p));
    return a;
}
#define SWZ(b) ((b) ^ (((b) >> 3) & 0x70))

__device__ __forceinline__ void cp16(uint32_t dst, const void* src) {
    asm volatile("cp.async.cg.shared.global [%0], [%1], 16;" :: "r"(dst), "l"(src));
}
#define CP_COMMIT() asm volatile("cp.async.commit_group;" ::: "memory")
#define CP_WAIT1()  asm volatile("cp.async.wait_group 1;" ::: "memory")
#define CP_WAIT0()  asm volatile("cp.async.wait_group 0;" ::: "memory")

__device__ __forceinline__ void ldsm4(uint32_t (&r)[4], uint32_t addr) {
    asm volatile("ldmatrix.sync.aligned.m8n8.x4.shared.b16 {%0,%1,%2,%3}, [%4];"
                 : "=r"(r[0]), "=r"(r[1]), "=r"(r[2]), "=r"(r[3]) : "r"(addr));
}
__device__ __forceinline__ void mma16816(float (&c)[4], const uint32_t (&a)[4],
                                         uint32_t b0, uint32_t b1) {
    asm volatile(
        "mma.sync.aligned.m16n8k16.row.col.f32.f16.f16.f32 "
        "{%0,%1,%2,%3}, {%4,%5,%6,%7}, {%8,%9}, {%0,%1,%2,%3};"
        : "+f"(c[0]), "+f"(c[1]), "+f"(c[2]), "+f"(c[3])
        : "r"(a[0]), "r"(a[1]), "r"(a[2]), "r"(a[3]), "r"(b0), "r"(b1));
}

// Device-wide barrier (all NCTAS CTAs resident by construction).
__device__ __forceinline__ void gbar(unsigned target) {
    __syncthreads();
    if (threadIdx.x == 0) {
        __threadfence();
        atomicAdd(&g_bar, 1u);
        while (*((volatile unsigned*)&g_bar) < target) { }
    }
    __syncthreads();
}

// ---------------- one-time prep ----------------
__global__ void k_zero_state() {
    int i = blockIdx.x * blockDim.x + threadIdx.x;
    if (i < FQ * HD) { g_h16A[i] = __float2half(0.f); g_c[i] = 0.f; }
    if (i == 0) g_bar = 0;
}

__global__ void k_conv_w(const float* __restrict__ W, int which) {
    __half* o = (which == 0) ? g_Wr_in : (which == 1) ? g_Wr_out
              : (which == 2) ? g_Wr_p : g_Wr_ihp;
    int idx = blockIdx.x * blockDim.x + threadIdx.x;
    if (idx >= N4 * HD) return;
    int n = idx >> 10, k = idx & 1023;
    int gate, j; colmap(n, gate, j);
    o[idx] = __float2half(W[(size_t)(gate * HD + j) * HD + k]);
}

__global__ void k_xe(const float* __restrict__ E, const float* __restrict__ Wih,
                     const float* __restrict__ b, int which) {
    float* XE = which ? g_XE_out : g_XE_in;
    int idx = blockIdx.x * blockDim.x + threadIdx.x;
    if (idx >= 128 * N4) return;
    int v = idx >> 12, n = idx & 4095;
    int gate, j; colmap(n, gate, j);
    int row = gate * HD + j;
    const float4* e = (const float4*)(E + v * EMBD);
    const float4* w = (const float4*)(Wih + (size_t)row * EMBD);
    float s = b[row];
    #pragma unroll 8
    for (int k = 0; k < EMBD / 4; k++) {
        float4 a = e[k], c = w[k];
        s += a.x * c.x + a.y * c.y + a.z * c.z + a.w * c.w;
    }
    XE[idx] = s;
}

__global__ void k_bias_p(const float* __restrict__ b) {
    int n = blockIdx.x * blockDim.x + threadIdx.x;
    if (n >= N4) return;
    int gate, j; colmap(n, gate, j);
    g_bg_p[n] = b[gate * HD + j];
}

__global__ void k_transpose1024(const float* __restrict__ W, int which) {
    float* Wt = which ? g_Wt_sm : g_Wt_mp;
    int idx = blockIdx.x * blockDim.x + threadIdx.x;
    if (idx >= HD * HD) return;
    int k = idx >> 10, n = idx & 1023;
    Wt[idx] = W[n * HD + k];
}

// ---------------- persistent kernel building blocks ----------------
__device__ __forceinline__ void loadW(uint32_t wsm, const __half* __restrict__ Wsrc,
                                      int n0, int tid) {
    #pragma unroll
    for (int o = 0; o < 32; o++) {
        int chunk = tid + o * 256;        // 0..8191
        int ti = chunk >> 9;
        int rem = chunk & 511;
        int r = rem >> 3, c16 = rem & 7;
        cp16(wsm + ti * 8192 + SWZ(r * 128 + c16 * 16),
             Wsrc + (size_t)(n0 + r) * HD + ti * 64 + c16 * 8);
    }
    CP_COMMIT();
    CP_WAIT0();
    __syncthreads();
}

__device__ __forceinline__ void loadA(uint32_t dst, const __half* __restrict__ hprev,
                                      int m0, int ti, int tid) {
    #pragma unroll
    for (int o = 0; o < 8; o++) {
        int chunk = tid + o * 256;        // 0..2047
        int r = chunk >> 3, c16 = chunk & 7;
        cp16(dst + SWZ(r * 128 + c16 * 16),
             hprev + (size_t)(m0 + r) * HD + ti * 64 + c16 * 8);
    }
    CP_COMMIT();
}

// One GEMM step: gates = hprev @ Wsm^T. MODE 0: char LSTM cell (XE gather + mask),
// MODE 1: XP = acc + b_p -> g_XP, MODE 2: program LSTM cell (XP addend, no mask).
template<int MODE>
__device__ __forceinline__ void do_step(
    uint32_t wsm, const uint32_t* sA,
    const __half* __restrict__ hprev, __half* __restrict__ hout,
    const float* __restrict__ xe, const int* __restrict__ tokens,
    const int* __restrict__ lengths, int t,
    int m0, int n0, int wm, int wn, int lane, int tid)
{
    float C[4][4][4] = {};

    loadA(sA[0], hprev, m0, 0, tid);
    loadA(sA[1], hprev, m0, 1, tid);

    for (int u = 0; u < PKT; u++) {
        if (u < PKT - 1) CP_WAIT1(); else CP_WAIT0();
        __syncthreads();
        if (u + 2 < PKT) loadA(sA[(u + 2) % 3], hprev, m0, u + 2, tid);

        uint32_t aB = sA[u % 3];
        uint32_t bB = wsm + u * 8192;
        #pragma unroll
        for (int kk = 0; kk < 4; kk++) {
            uint32_t ra[4][4], rb[2][4];
            #pragma unroll
            for (int mt = 0; mt < 4; mt++)
                ldsm4(ra[mt], aB + SWZ((wm * 64 + mt * 16 + (lane & 15)) * 128
                                       + (kk * 16 + (lane >> 4) * 8) * 2));
            #pragma unroll
            for (int np = 0; np < 2; np++)
                ldsm4(rb[np], bB + SWZ((wn * 32 + np * 16 + ((lane >> 4) & 1) * 8 + (lane & 7)) * 128
                                       + (kk * 16 + ((lane >> 3) & 1) * 8) * 2));
            #pragma unroll
            for (int mt = 0; mt < 4; mt++) {
                #pragma unroll
                for (int np = 0; np < 2; np++) {
                    mma16816(C[mt][2 * np + 0], ra[mt], rb[np][0], rb[np][1]);
                    mma16816(C[mt][2 * np + 1], ra[mt], rb[np][2], rb[np][3]);
                }
            }
        }
    }

    // epilogue
    int r0 = lane >> 2;
    int cpair = (lane & 3) * 2;
    int nwarp0 = n0 + wn * 32;
    int jbase = (nwarp0 >> 5) * 8 + (lane & 3) * 2;

    #pragma unroll
    for (int mt = 0; mt < 4; mt++) {
        #pragma unroll
        for (int rowsel = 0; rowsel < 2; rowsel++) {
            int m = m0 + wm * 64 + mt * 16 + r0 + rowsel * 8;
            int rg = rowsel * 2;
            if (MODE == 1) {
                #pragma unroll
                for (int u = 0; u < 2; u++) {
                    int n_if = nwarp0 + u * 16 + cpair;
                    float2 v0 = make_float2(C[mt][2 * u + 0][rg + 0] + g_bg_p[n_if],
                                            C[mt][2 * u + 0][rg + 1] + g_bg_p[n_if + 1]);
                    float2 v1 = make_float2(C[mt][2 * u + 1][rg + 0] + g_bg_p[n_if + 8],
                                            C[mt][2 * u + 1][rg + 1] + g_bg_p[n_if + 9]);
                    *(float2*)(g_XP + (size_t)m * N4 + n_if) = v0;
                    *(float2*)(g_XP + (size_t)m * N4 + n_if + 8) = v1;
                }
            } else {
                const float* base;
                bool act = true;
                if (MODE == 0) {
                    int tok = tokens[m * LQ + t];
                    base = xe + (size_t)tok * N4;
                    act = (t < lengths[m]);
                } else {
                    base = g_XP + (size_t)m * N4;
                }
                size_t hidx = (size_t)m * HD + jbase;
                if (act) {
                    float hv[2];
                    float2 cold = *(float2*)(g_c + hidx);
                    float cvals[2] = { cold.x, cold.y };
                    #pragma unroll
                    for (int u = 0; u < 2; u++) {
                        int n_if = nwarp0 + u * 16 + cpair;
                        float2 aif = *(const float2*)(base + n_if);
                        float2 ago = *(const float2*)(base + n_if + 8);
                        float gi = C[mt][2 * u + 0][rg + 0] + aif.x;
                        float gf = C[mt][2 * u + 0][rg + 1] + aif.y;
                        float gg = C[mt][2 * u + 1][rg + 0] + ago.x;
                        float go = C[mt][2 * u + 1][rg + 1] + ago.y;
                        float cn = sigf(gf) * cvals[u] + sigf(gi) * tanhf(gg);
                        hv[u] = sigf(go) * tanhf(cn);
                        cvals[u] = cn;
                    }
                    *(float2*)(g_c + hidx) = make_float2(cvals[0], cvals[1]);
                    *(__half2*)(hout + hidx) = __floats2half2_rn(hv[0], hv[1]);
                } else {
                    *(__half2*)(hout + hidx) = *(const __half2*)(hprev + hidx);
                }
            }
        }
    }
}

// ---------------- the persistent kernel ----------------
__global__ void __launch_bounds__(256, 1)
k_persist(const int* __restrict__ ti_, const int* __restrict__ li_,
          const int* __restrict__ to_, const int* __restrict__ lo_) {
    extern __shared__ char smem[];
    uint32_t sbase = smem_u32(smem);
    uint32_t wsm = sbase;
    uint32_t sA[3] = { sbase + W_BYTES, sbase + W_BYTES + A_STAGE, sbase + W_BYTES + 2 * A_STAGE };

    int tid = threadIdx.x;
    int lane = tid & 31, wid = tid >> 5;
    int wm = wid >> 1, wn = wid & 1;
    int n0 = blockIdx.x * PTN;
    int m0 = blockIdx.y * PTM;

    unsigned epoch = 0;
    int cur = 0;

    // phase 1: input char LSTM
    loadW(wsm, g_Wr_in, n0, tid);
    for (int t = 0; t < LQ; t++) {
        const __half* hin = cur ? g_h16B : g_h16A;
        __half* hout = cur ? g_h16A : g_h16B;
        do_step<0>(wsm, sA, hin, hout, g_XE_in, ti_, li_, t, m0, n0, wm, wn, lane, tid);
        cur ^= 1;
        epoch++; gbar(epoch * NCTAS);
    }

    // phase 2: output char LSTM
    loadW(wsm, g_Wr_out, n0, tid);
    for (int t = 0; t < LQ; t++) {
        const __half* hin = cur ? g_h16B : g_h16A;
        __half* hout = cur ? g_h16A : g_h16B;
        do_step<0>(wsm, sA, hin, hout, g_XE_out, to_, lo_, t, m0, n0, wm, wn, lane, tid);
        cur ^= 1;
        epoch++; gbar(epoch * NCTAS);
    }

    const __half* hfin = cur ? g_h16B : g_h16A;

    // phase 3: XP = hfin @ W_ih_p^T + b_p (CTA-owned writes; no barrier needed)
    loadW(wsm, g_Wr_ihp, n0, tid);
    do_step<1>(wsm, sA, hfin, nullptr, nullptr, nullptr, nullptr, 0, m0, n0, wm, wn, lane, tid);

    // phase 4: program LSTM
    loadW(wsm, g_Wr_p, n0, tid);
    for (int s = 0; s < PLENQ; s++) {
        const __half* hp = s ? (g_hsteps + (size_t)(s - 1) * FQ * HD) : hfin;
        __half* ho = g_hsteps + (size_t)s * FQ * HD;
        do_step<2>(wsm, sA, hp, ho, nullptr, nullptr, nullptr, 0, m0, n0, wm, wn, lane, tid);
        epoch++; gbar(epoch * NCTAS);
    }
}

// ---------------- batched SIMT epilogue GEMMs ----------------
__global__ __launch_bounds__(NT)
void k_mp(const float* __restrict__ bmp) {
    int s = blockIdx.z;
    const __half* __restrict__ hcur = g_hsteps + (size_t)s * FQ * HD;
    float* __restrict__ pool = g_pooled + (size_t)s * BQ * HD;
    __shared__ float As[BK][BM + 4];
    __shared__ float Bs[BK][BN];
    int tid = threadIdx.x;
    int m0 = blockIdx.y * BM, n0 = blockIdx.x * BN;
    float acc[4][4] = {};
    int ma = tid >> 2, k4 = (tid & 3) * 4;
    int kb = tid >> 4, n4 = (tid & 15) * 4;
    int ty = tid >> 4, tx = tid & 15;
    for (int k0 = 0; k0 < HD; k0 += BK) {
        __half2 p0 = *(const __half2*)(hcur + (m0 + ma) * HD + k0 + k4);
        __half2 p1 = *(const __half2*)(hcur + (m0 + ma) * HD + k0 + k4 + 2);
        float2 f0 = __half22float2(p0), f1 = __half22float2(p1);
        float4 bv = *(const float4*)(g_Wt_mp + (k0 + kb) * HD + n0 + n4);
        As[k4 + 0][ma] = f0.x; As[k4 + 1][ma] = f0.y;
        As[k4 + 2][ma] = f1.x; As[k4 + 3][ma] = f1.y;
        *(float4*)&Bs[kb][n4] = bv;
        __syncthreads();
        #pragma unroll
        for (int k = 0; k < BK; k++) {
            float4 a = *(const float4*)&As[k][ty * 4];
            float4 b = *(const float4*)&Bs[k][tx * 4];
            acc[0][0] += a.x * b.x; acc[0][1] += a.x * b.y; acc[0][2] += a.x * b.z; acc[0][3] += a.x * b.w;
            acc[1][0] += a.y * b.x; acc[1][1] += a.y * b.y; acc[1][2] += a.y * b.z; acc[1][3] += a.y * b.w;
            acc[2][0] += a.z * b.x; acc[2][1] += a.z * b.y; acc[2][2] += a.z * b.z; acc[2][3] += a.z * b.w;
            acc[3][0] += a.w * b.x; acc[3][1] += a.w * b.y; acc[3][2] += a.w * b.z; acc[3][3] += a.w * b.w;
        }
        __syncthreads();
    }
    float4 bb = *(const float4*)(bmp + n0 + tx * 4);
    float4 mx; mx.x = mx.y = mx.z = mx.w = -2.f;
    #pragma unroll
    for (int r = 0; r < 4; r++) {
        mx.x = fmaxf(mx.x, tanhf(acc[r][0] + bb.x));
        mx.y = fmaxf(mx.y, tanhf(acc[r][1] + bb.y));
        mx.z = fmaxf(mx.z, tanhf(acc[r][2] + bb.z));
        mx.w = fmaxf(mx.w, tanhf(acc[r][3] + bb.w));
    }
    int b = (m0 >> 2) + ty;
    *(float4*)(pool + b * HD + n0 + tx * 4) = mx;
}

__global__ __launch_bounds__(NT)
void k_logits(const float* __restrict__ bsm, float* __restrict__ out) {
    int s = blockIdx.z;
    const float* __restrict__ pool = g_pooled + (size_t)s * BQ * HD;
    __shared__ float As[BK][BM + 4];
    __shared__ float Bs[BK][BN];
    int tid = threadIdx.x;
    int m0 = blockIdx.y * BM, n0 = blockIdx.x * BN;
    float acc[4][4] = {};
    int ma = tid >> 2, k4 = (tid & 3) * 4;
    int kb = tid >> 4, n4 = (tid & 15) * 4;
    int ty = tid >> 4, tx = tid & 15;
    for (int k0 = 0; k0 < HD; k0 += BK) {
        float4 av = *(const float4*)(pool + (m0 + ma) * HD + k0 + k4);
        float4 bv = *(const float4*)(g_Wt_sm + (k0 + kb) * PQ + n0 + n4);
        As[k4 + 0][ma] = av.x; As[k4 + 1][ma] = av.y;
        As[k4 + 2][ma] = av.z; As[k4 + 3][ma] = av.w;
        *(float4*)&Bs[kb][n4] = bv;
        __syncthreads();
        #pragma unroll
        for (int k = 0; k < BK; k++) {
            float4 a = *(const float4*)&As[k][ty * 4];
            float4 b = *(const float4*)&Bs[k][tx * 4];
            acc[0][0] += a.x * b.x; acc[0][1] += a.x * b.y; acc[0][2] += a.x * b.z; acc[0][3] += a.x * b.w;
            acc[1][0] += a.y * b.x; acc[1][1] += a.y * b.y; acc[1][2] += a.y * b.z; acc[1][3] += a.y * b.w;
            acc[2][0] += a.z * b.x; acc[2][1] += a.z * b.y; acc[2][2] += a.z * b.z; acc[2][3] += a.z * b.w;
            acc[3][0] += a.w * b.x; acc[3][1] += a.w * b.y; acc[3][2] += a.w * b.z; acc[3][3] += a.w * b.w;
        }
        __syncthreads();
    }
    float4 bb = *(const float4*)(bsm + n0 + tx * 4);
    #pragma unroll
    for (int r = 0; r < 4; r++) {
        int m = m0 + ty * 4 + r;
        float4 v;
        v.x = acc[r][0] + bb.x; v.y = acc[r][1] + bb.y;
        v.z = acc[r][2] + bb.z; v.w = acc[r][3] + bb.w;
        *(float4*)(out + (size_t)s * BQ * PQ + m * PQ + n0 + tx * 4) = v;
    }
}

// ---------------- host orchestration ----------------
extern "C" void kernel_launch(void* const* d_in, const int* in_sizes, int n_in,
                              void* d_out, int out_size) {
    const int*   tokens_in   = (const int*)d_in[0];
    const int*   lengths_in  = (const int*)d_in[1];
    const int*   tokens_out  = (const int*)d_in[2];
    const int*   lengths_out = (const int*)d_in[3];
    const float* emb         = (const float*)d_in[4];
    const float* W_ih_in     = (const float*)d_in[5];
    const float* W_hh_in     = (const float*)d_in[6];
    const float* b_in        = (const float*)d_in[7];
    const float* W_ih_out    = (const float*)d_in[8];
    const float* W_hh_out    = (const float*)d_in[9];
    const float* b_out       = (const float*)d_in[10];
    const float* W_ih_p      = (const float*)d_in[11];
    const float* W_hh_p      = (const float*)d_in[12];
    const float* b_p         = (const float*)d_in[13];
    const float* W_mp        = (const float*)d_in[14];
    const float* b_mp        = (const float*)d_in[15];
    const float* W_sm        = (const float*)d_in[16];
    const float* b_sm        = (const float*)d_in[17];
    float* out = (float*)d_out;

    static int smem_set = 0;
    if (!smem_set) {
        cudaFuncSetAttribute(k_persist, cudaFuncAttributeMaxDynamicSharedMemorySize, SMEM_P);
        smem_set = 1;
    }

    k_zero_state<<<(FQ * HD + 255) / 256, 256>>>();
    k_conv_w<<<(N4 * HD + 255) / 256, 256>>>(W_hh_in,  0);
    k_conv_w<<<(N4 * HD + 255) / 256, 256>>>(W_hh_out, 1);
    k_conv_w<<<(N4 * HD + 255) / 256, 256>>>(W_hh_p,   2);
    k_conv_w<<<(N4 * HD + 255) / 256, 256>>>(W_ih_p,   3);
    k_xe<<<(128 * N4 + 255) / 256, 256>>>(emb, W_ih_in,  b_in,  0);
    k_xe<<<(128 * N4 + 255) / 256, 256>>>(emb, W_ih_out, b_out, 1);
    k_bias_p<<<(N4 + 255) / 256, 256>>>(b_p);
    k_transpose1024<<<(HD * HD + 255) / 256, 256>>>(W_mp, 0);
    k_transpose1024<<<(HD * PQ + 255) / 256, 256>>>(W_sm, 1);

    k_persist<<<dim3(GRIDX, GRIDY), 256, SMEM_P>>>(tokens_in, lengths_in,
                                                   tokens_out, lengths_out);

    k_mp<<<dim3(HD / BN, FQ / BM, PLENQ), NT>>>(b_mp);
    k_logits<<<dim3(PQ / BN, BQ / BM, PLENQ), NT>>>(b_sm, out);
}